// round 7
// baseline (speedup 1.0000x reference)
#include <cuda_runtime.h>
#include <math.h>

constexpr int kN   = 50000;
constexpr int kE   = 800000;
constexpr int kG   = 512;
constexpr int kD   = 128;
constexpr int kEE  = 64;
constexpr int kL   = 4;
constexpr int kNC  = 10;
constexpr int kSB  = (kN + 1023) / 1024;
constexpr float kBNS = 0.9999950000374997f;  // (1+1e-5)^-0.5

typedef unsigned long long u64;

// ---------------- f32x2 packed helpers -------------------------------------
__device__ __forceinline__ u64 pack2(float lo, float hi) {
    u64 r; asm("mov.b64 %0,{%1,%2};" : "=l"(r) : "f"(lo), "f"(hi)); return r;
}
__device__ __forceinline__ u64 splat2(float v) { return pack2(v, v); }
__device__ __forceinline__ void unpack2(u64 p, float& lo, float& hi) {
    asm("mov.b64 {%0,%1},%2;" : "=f"(lo), "=f"(hi) : "l"(p));
}
__device__ __forceinline__ u64 fma2(u64 a, u64 b, u64 c) {
    u64 r; asm("fma.rn.f32x2 %0,%1,%2,%3;" : "=l"(r) : "l"(a), "l"(b), "l"(c)); return r;
}
__device__ __forceinline__ u64 add2(u64 a, u64 b) {
    u64 r; asm("add.rn.f32x2 %0,%1,%2;" : "=l"(r) : "l"(a), "l"(b)); return r;
}

// ---------------- scratch ----------------------------------------------------
__device__ float g_x[kN * kD];
__device__ float g_xl[kN * kD];
__device__ float g_xr[kN * kD];
__device__ float g_lraw[kN * 8];
__device__ int   g_deg[kN];
__device__ int   g_cur[kN];
__device__ int   g_scan[kN];
__device__ int   g_bt[kSB];
__device__ int   g_boff[kSB];
__device__ int   g_off[kN + 1];
__device__ int   g_csrc[kE];
__device__ float g_eraw[(size_t)kE * 8];
__device__ float g_M[kL * 8 * kD];
__device__ float g_bep[kL * kD];
__device__ float g_gsum[kG * kD];

// ---------------- 1: init + node encode --------------------------------------
__global__ void init_enc(const int* __restrict__ xn, const float* __restrict__ emb) {
    int i = blockIdx.x * blockDim.x + threadIdx.x;
    int stride = gridDim.x * blockDim.x;
    for (int t = i; t < kN; t += stride) { g_deg[t] = 0; g_cur[t] = 0; }
    for (int t = i; t < kN * kD; t += stride) {
        int n = t >> 7, j = t & 127;
        g_x[t] = emb[xn[n] * kD + j];
    }
}

// ---------------- 2: degree count --------------------------------------------
__global__ void count_deg(const int* __restrict__ src, const int* __restrict__ dst) {
    int e = blockIdx.x * blockDim.x + threadIdx.x;
    if (e >= kE) return;
    int s = src[e], d = dst[e];
    if (s != d) atomicAdd(&g_deg[d], 1);
}

// ---------------- scan -------------------------------------------------------
__global__ void scan1() {
    __shared__ int sh[1024];
    int n = blockIdx.x * 1024 + threadIdx.x;
    int v = (n < kN) ? g_deg[n] : 0;
    sh[threadIdx.x] = v;
    __syncthreads();
    for (int o = 1; o < 1024; o <<= 1) {
        int add = (threadIdx.x >= o) ? sh[threadIdx.x - o] : 0;
        __syncthreads();
        sh[threadIdx.x] += add;
        __syncthreads();
    }
    if (n < kN) g_scan[n] = sh[threadIdx.x];
    if (threadIdx.x == 1023) g_bt[blockIdx.x] = sh[1023];
}
__global__ void scan2() {
    if (threadIdx.x == 0) {
        int run = 0;
        for (int b = 0; b < kSB; b++) { g_boff[b] = run; run += g_bt[b]; }
        g_off[kN] = run;
    }
}
__global__ void scan3() {
    int n = blockIdx.x * blockDim.x + threadIdx.x;
    if (n < kN) g_off[n] = g_scan[n] - g_deg[n] + g_boff[n >> 10];
}

// ---------------- 4 (PROFILED): xl/xr GEMM -----------------------------------
__global__ __launch_bounds__(256) void xlr_gemm(
        const float* __restrict__ Wl, const float* __restrict__ bl,
        const float* __restrict__ Wr, const float* __restrict__ br, int layer) {
    const float* W = (blockIdx.y == 0 ? Wl : Wr) + layer * kD * kD;
    const float* bias = (blockIdx.y == 0 ? bl : br) + layer * kD;
    float* out = blockIdx.y == 0 ? g_xl : g_xr;

    __shared__ __align__(16) float ws[32 * 128];
    __shared__ __align__(16) float xs[32][68];

    int t = threadIdx.x;
    int lane = t & 31;
    int w = t >> 5;
    int n0 = blockIdx.x * 64;

    u64 acc[8][2] = {};
    for (int kt = 0; kt < kD; kt += 32) {
#pragma unroll
        for (int r = t; r < 32 * 128; r += 256)
            ws[r] = W[(kt + (r >> 7)) * kD + (r & 127)];
#pragma unroll
        for (int r = t; r < 64 * 32; r += 256) {
            int n = r >> 5, kk = r & 31;
            int nn = n0 + n;
            xs[kk][n] = (nn < kN) ? g_x[nn * kD + kt + kk] : 0.f;
        }
        __syncthreads();
#pragma unroll
        for (int kk = 0; kk < 32; kk++) {
            ulonglong2 wv = *(const ulonglong2*)&ws[kk * 128 + lane * 4];
            float4 xv0 = *(const float4*)&xs[kk][w * 8];
            float4 xv1 = *(const float4*)&xs[kk][w * 8 + 4];
            float xm[8] = {xv0.x, xv0.y, xv0.z, xv0.w, xv1.x, xv1.y, xv1.z, xv1.w};
#pragma unroll
            for (int m = 0; m < 8; m++) {
                u64 xp = splat2(xm[m]);
                acc[m][0] = fma2(xp, wv.x, acc[m][0]);
                acc[m][1] = fma2(xp, wv.y, acc[m][1]);
            }
        }
        __syncthreads();
    }
    float4 bv = *(const float4*)(bias + lane * 4);
#pragma unroll
    for (int m = 0; m < 8; m++) {
        int n = n0 + w * 8 + m;
        if (n < kN) {
            float a0, a1, a2, a3;
            unpack2(acc[m][0], a0, a1);
            unpack2(acc[m][1], a2, a3);
            float4 o = make_float4(a0 + bv.x, a1 + bv.y, a2 + bv.z, a3 + bv.w);
            *(float4*)&out[n * kD + lane * 4] = o;
        }
    }
}

// ---------------- scatter CSR + permute raw edge attrs ----------------------
__global__ void scatter_csr(const int* __restrict__ src, const int* __restrict__ dst,
                            const float* __restrict__ eattr) {
    int e = blockIdx.x * blockDim.x + threadIdx.x;
    if (e >= kE) return;
    int s = src[e], d = dst[e];
    if (s == d) return;
    int pos = atomicAdd(&g_cur[d], 1);
    int idx = g_off[d] + pos;
    g_csrc[idx] = s;
    float4 a = *(const float4*)&eattr[(size_t)e * 8];
    float4 b = *(const float4*)&eattr[(size_t)e * 8 + 4];
    *(float4*)&g_eraw[(size_t)idx * 8] = a;
    *(float4*)&g_eraw[(size_t)idx * 8 + 4] = b;
}

// ---------------- lraw + M/bep for all layers -------------------------------
__global__ void prep(const float* __restrict__ eW, const float* __restrict__ eb,
                     const float* __restrict__ We) {
    int nbl = (kN * 8 + 1023) / 1024;
    if ((int)blockIdx.x < nbl) {
        int t = blockIdx.x * 1024 + threadIdx.x;
        int n = t >> 3, j = t & 7;
        if (n >= kN) return;
        int beg = g_off[n], end = g_off[n + 1];
        float s = 0.f;
        for (int idx = beg; idx < end; idx++) s += g_eraw[(size_t)idx * 8 + j];
        int c = end - beg;
        g_lraw[n * 8 + j] = s / (float)(c > 1 ? c : 1);
    } else {
        int layer = blockIdx.x - nbl;
        int t = threadIdx.x;
        int k = t >> 7, j = t & 127;
        const float* w = We + (size_t)layer * kEE * kD;
        float acc = 0.f;
#pragma unroll 8
        for (int u = 0; u < kEE; u++) acc += eW[k * kEE + u] * w[u * kD + j];
        g_M[layer * 8 * kD + k * kD + j] = acc;
        if (t < kD) {
            float b = 0.f;
#pragma unroll 8
            for (int u = 0; u < kEE; u++) b += eb[u] * w[u * kD + t];
            g_bep[layer * kD + t] = b;
        }
    }
}

// ---------------- fused GAT: 2 warps per node (4 heads / 64 dims each) ------
__global__ __launch_bounds__(128) void fused_gat(
        const float* __restrict__ att, const float* __restrict__ gbias,
        const float* __restrict__ gam, const float* __restrict__ bet, int layer) {
    int t = threadIdx.x, lane = t & 31;
    int gw = (blockIdx.x * 128 + t) >> 5;   // global warp id
    int d = gw >> 1;
    if (d >= kN) return;
    int half = gw & 1;
    int j0 = half * 64 + lane * 2;          // this lane's 2 dims

    // M rows for this lane's 2 columns (8 u64 regs)
    u64 Mr[8];
#pragma unroll
    for (int k = 0; k < 8; k++) {
        float2 mv = *(const float2*)&g_M[layer * 8 * kD + k * kD + j0];
        Mr[k] = pack2(mv.x, mv.y);
    }
    float2 attv = *(const float2*)&att[layer * kD + j0];
    float2 bep2 = *(const float2*)&g_bep[layer * kD + j0];
    float2 xld2 = *(const float2*)&g_xl[d * kD + j0];
    u64 xld = pack2(xld2.x, xld2.y);

    int beg = g_off[d], end = g_off[d + 1];

    float2 gb = *(const float2*)&gbias[layer * kD + j0];
    float2 gm = *(const float2*)&gam[layer * kD + j0];
    float2 bt = *(const float2*)&bet[layer * kD + j0];

    float a0, a1;
    if (beg == end) {
        a0 = xld2.x; a1 = xld2.y;
    } else {
        float2 xr2 = *(const float2*)&g_xr[d * kD + j0];
        u64 xrb = pack2(xr2.x + bep2.x, xr2.y + bep2.y);

        // ---- self-loop logit = fixed softmax shift ----
        float4 lr1 = *(const float4*)&g_lraw[d * 8];
        float4 lr2 = *(const float4*)&g_lraw[d * 8 + 4];
        u64 e0 = xrb;
        {
            float rk[8] = {lr1.x, lr1.y, lr1.z, lr1.w, lr2.x, lr2.y, lr2.z, lr2.w};
#pragma unroll
            for (int k = 0; k < 8; k++) e0 = fma2(splat2(rk[k]), Mr[k], e0);
        }
        e0 = add2(e0, xld);
        float vx, vy;
        unpack2(e0, vx, vy);
        vx = fmaxf(vx, 0.2f * vx); vy = fmaxf(vy, 0.2f * vy);
        float lself = vx * attv.x + vy * attv.y;
        lself += __shfl_xor_sync(0xffffffffu, lself, 1);
        lself += __shfl_xor_sync(0xffffffffu, lself, 2);
        lself += __shfl_xor_sync(0xffffffffu, lself, 4);

        float den = 1.f;
        u64 acc = xld;

        // ---- feed-forward edge loop, depth-2 prefetch, late xl consumption --
        int i = beg;
        int sN = g_csrc[i];
        float4 raN = *(const float4*)&g_eraw[(size_t)i * 8];
        float4 rbN = *(const float4*)&g_eraw[(size_t)i * 8 + 4];
        float2 xlN = *(const float2*)&g_xl[sN * kD + j0];
        int sNN = 0; float4 raNN = {}, rbNN = {};
        if (i + 1 < end) {
            sNN = g_csrc[i + 1];
            raNN = *(const float4*)&g_eraw[(size_t)(i + 1) * 8];
            rbNN = *(const float4*)&g_eraw[(size_t)(i + 1) * 8 + 4];
        }
        for (; i < end; i++) {
            float2 xls = xlN;
            float4 ra = raN, rb = rbN;
            if (i + 1 < end) {
                xlN = *(const float2*)&g_xl[sNN * kD + j0];
                raN = raNN; rbN = rbNN;
            }
            if (i + 2 < end) {
                sNN = g_csrc[i + 2];
                raNN = *(const float4*)&g_eraw[(size_t)(i + 2) * 8];
                rbNN = *(const float4*)&g_eraw[(size_t)(i + 2) * 8 + 4];
            }
            // ep from edge attrs first (independent of the xl gather)
            u64 f = xrb;
            float rk[8] = {ra.x, ra.y, ra.z, ra.w, rb.x, rb.y, rb.z, rb.w};
#pragma unroll
            for (int k = 0; k < 8; k++) f = fma2(splat2(rk[k]), Mr[k], f);
            // consume gathered xl[s] as late as possible
            u64 xlsp = pack2(xls.x, xls.y);
            f = add2(f, xlsp);
            float ax, ay;
            unpack2(f, ax, ay);
            ax = fmaxf(ax, 0.2f * ax); ay = fmaxf(ay, 0.2f * ay);
            float l2 = ax * attv.x + ay * attv.y;
            l2 += __shfl_xor_sync(0xffffffffu, l2, 1);
            l2 += __shfl_xor_sync(0xffffffffu, l2, 2);
            l2 += __shfl_xor_sync(0xffffffffu, l2, 4);

            float p = __expf(l2 - lself);
            den += p;
            acc = fma2(splat2(p), xlsp, acc);
        }
        float inv = 1.f / den;
        float c0, c1;
        unpack2(acc, c0, c1);
        a0 = c0 * inv; a1 = c1 * inv;
    }

    float w0 = gm.x * (a0 + gb.x) * kBNS + bt.x;
    float w1 = gm.y * (a1 + gb.y) * kBNS + bt.y;
    float2 o;
    o.x = w0 > 0.f ? w0 : expm1f(w0);
    o.y = w1 > 0.f ? w1 : expm1f(w1);
    *(float2*)&g_x[d * kD + j0] = o;
}

// ---------------- pool + head ------------------------------------------------
__global__ void pool(const int* __restrict__ batch) {
    int g = blockIdx.x;
    int t = threadIdx.x;   // 128
    __shared__ int slo, shi;
    if (t == 0) {
        int lo = 0, hi = kN;
        while (lo < hi) { int mid = (lo + hi) >> 1; if (batch[mid] < g) lo = mid + 1; else hi = mid; }
        slo = lo;
        hi = kN;
        while (lo < hi) { int mid = (lo + hi) >> 1; if (batch[mid] < g + 1) lo = mid + 1; else hi = mid; }
        shi = lo;
    }
    __syncthreads();
    int lo = slo, hi = shi;
    float s = 0.f;
    for (int n = lo; n < hi; n++) s += g_x[n * kD + t];
    g_gsum[g * kD + t] = s / fmaxf((float)(hi - lo), 1.f);
}

__global__ void head(const float* __restrict__ hW, const float* __restrict__ hb,
                     float* __restrict__ out) {
    int g = blockIdx.x;
    int lane = threadIdx.x;
    float acc[kNC] = {};
    for (int k = lane; k < kD; k += 32) {
        float mm = g_gsum[g * kD + k];
#pragma unroll
        for (int c = 0; c < kNC; c++) acc[c] += mm * hW[k * kNC + c];
    }
#pragma unroll
    for (int c = 0; c < kNC; c++) {
        float v = acc[c];
#pragma unroll
        for (int o = 16; o > 0; o >>= 1) v += __shfl_down_sync(0xffffffffu, v, o);
        if (lane == 0) out[g * kNC + c] = v + hb[c];
    }
}

// ---------------- launch -----------------------------------------------------
extern "C" void kernel_launch(void* const* d_in, const int* in_sizes, int n_in,
                              void* d_out, int out_size) {
    const int*   x_nodes = (const int*)d_in[0];
    const int*   esrc    = (const int*)d_in[1];
    const int*   edst    = (const int*)d_in[2];
    const float* eattr   = (const float*)d_in[3];
    const int*   batch   = (const int*)d_in[4];
    const float* nemb    = (const float*)d_in[5];
    const float* edge_W  = (const float*)d_in[6];
    const float* edge_b  = (const float*)d_in[7];
    const float* Wl      = (const float*)d_in[8];
    const float* bl      = (const float*)d_in[9];
    const float* Wr      = (const float*)d_in[10];
    const float* br      = (const float*)d_in[11];
    const float* We      = (const float*)d_in[12];
    const float* att     = (const float*)d_in[13];
    const float* gbias   = (const float*)d_in[14];
    const float* bng     = (const float*)d_in[15];
    const float* bnb     = (const float*)d_in[16];
    const float* headW   = (const float*)d_in[17];
    const float* headb   = (const float*)d_in[18];
    float* out = (float*)d_out;

    init_enc<<<4096, 256>>>(x_nodes, nemb);                        // 1
    count_deg<<<(kE + 255) / 256, 256>>>(esrc, edst);              // 2
    scan1<<<kSB, 1024>>>();                                        // 3
    xlr_gemm<<<dim3((kN + 63) / 64, 2), 256>>>(Wl, bl, Wr, br, 0); // 4 (profiled)
    scan2<<<1, 32>>>();                                            // 5
    scan3<<<(kN + 255) / 256, 256>>>();                            // 6
    scatter_csr<<<(kE + 255) / 256, 256>>>(esrc, edst, eattr);     // 7
    int nbl = (kN * 8 + 1023) / 1024;
    prep<<<nbl + kL, 1024>>>(edge_W, edge_b, We);                  // 8
    fused_gat<<<(kN * 2 * 32 + 127) / 128, 128>>>(att, gbias, bng, bnb, 0);

    for (int i = 1; i < kL; i++) {
        xlr_gemm<<<dim3((kN + 63) / 64, 2), 256>>>(Wl, bl, Wr, br, i);
        fused_gat<<<(kN * 2 * 32 + 127) / 128, 128>>>(att, gbias, bng, bnb, i);
    }

    pool<<<kG, kD>>>(batch);
    head<<<kG, 32>>>(headW, headb, out);
}